// round 12
// baseline (speedup 1.0000x reference)
#include <cuda_runtime.h>
#include <cuda_fp16.h>

#define NATOM 100000
#define MNBR  12
#define AF    64
#define BF    41
#define TWOA  128
#define NM    (NATOM*MNBR)          // 1200000
#define NMF   ((double)NM)
#define NF    ((double)NATOM)
#define EPSBN 1e-5
#define NT    (NM/96)               // 12500 tiles
#define PBLOCKS 444                 // persistent: 3 blocks/SM x 148 SMs

// ---- dynamic smem layout (bytes) for persistent kGemmStore ----
#define BT_PAD    104
#define OFF_WS    0                              // float Ws[41*128]        = 20992
#define OFF_BT    20992                          // float bT[41*104]        = 17056
#define OFF_BRAW  38048                          // float braw[2][3936]     = 31488
#define OFF_IDX   69536                          // int   idxS[2][96]       = 768
#define SMEM_BYTES 70304                         // x3 blocks = 210.9 KB
#define OFF_RED   OFF_BRAW                       // red: 8 warps x 128 x 2 x 4B = 8KB (overlay)

typedef unsigned long long ull;

// ---------------- scratch (device globals; no allocations) ----------------
__device__ float  d_SW[(size_t)NATOM*TWOA];      // atom @ W[0:64] + bias
__device__ float  d_PW[(size_t)NATOM*TWOA];      // atom @ W[64:128] (fp32)
__device__ ull    d_PW16[(size_t)NATOM*32];      // packed fp16 PW: lane l = {2l,2l+1,64+2l,64+2l+1}
__device__ ull    d_gated16[(size_t)NM*32];      // fp16 gated, same packing (307 MB)
__device__ float  d_summed[(size_t)NATOM*AF];
__device__ double d_s1[TWOA], d_q1[TWOA];
__device__ double d_s2[AF],   d_q2[AF];
__device__ float  d_g1[TWOA], d_h1[TWOA];
__device__ float  d_g2[AF],   d_h2[AF];
__device__ unsigned d_c1, d_c2;

// ---------------- helpers ----------------
__device__ __forceinline__ void ffma2(ull &d, ull a, ull b) {
    asm("fma.rn.f32x2 %0, %1, %2, %0;" : "+l"(d) : "l"(a), "l"(b));
}
__device__ __forceinline__ ull packdup(float x) {
    ull r; asm("mov.b64 %0, {%1, %1};" : "=l"(r) : "f"(x)); return r;
}
__device__ __forceinline__ float2 unpk(ull v) {
    float2 r; asm("mov.b64 {%0, %1}, %2;" : "=f"(r.x), "=f"(r.y) : "l"(v)); return r;
}
__device__ __forceinline__ float sigmoidf_(float x) {
    return __fdividef(1.0f, 1.0f + __expf(-x));
}
__device__ __forceinline__ float softplusf_(float x) {
    float e = __expf(-fabsf(x));
    return fmaxf(x, 0.0f) + __logf(1.0f + e);
}
__device__ __forceinline__ void cpasync16(void* dst_smem, const void* src) {
    unsigned s = (unsigned)__cvta_generic_to_shared(dst_smem);
    asm volatile("cp.async.cg.shared.global [%0], [%1], 16;" :: "r"(s), "l"(src) : "memory");
}
#define CP_COMMIT() asm volatile("cp.async.commit_group;" ::: "memory")
#define CP_WAIT(n)  asm volatile("cp.async.wait_group %0;" :: "n"(n) : "memory")

// ---------------- kInit ----------------
__global__ void kInit() {
    int t = threadIdx.x;
    if (t < TWOA) { d_s1[t] = 0.0; d_q1[t] = 0.0; }
    if (t < AF)   { d_s2[t] = 0.0; d_q2[t] = 0.0; }
    if (t == 0)   { d_c1 = 0u; d_c2 = 0u; }
}

// ---------------- kA: SW = atom@W1 + b, PW = atom@W2 ----------------
__global__ void __launch_bounds__(256) kA(const float* __restrict__ atom,
                                          const float* __restrict__ W,
                                          const float* __restrict__ bias) {
    __shared__ __align__(16) float at[64][132];
    int t = threadIdx.x;
    int aBase = blockIdx.x * 128;
    int aCount = NATOM - aBase; if (aCount > 128) aCount = 128;

    float wreg[64];
    const float* wp = (t < 128) ? (W + t) : (W + 64 * TWOA + (t - 128));
    #pragma unroll
    for (int k = 0; k < 64; k++) wreg[k] = wp[k * TWOA];
    float bj = (t < 128) ? bias[t] : 0.0f;

    for (int idx = t; idx < 128 * 64; idx += 256) {
        int a = idx >> 6, k = idx & 63;
        at[k][a] = (a < aCount) ? atom[(size_t)(aBase + a) * AF + k] : 0.0f;
    }
    __syncthreads();

    float* dst = (t < 128) ? d_SW : d_PW;
    int j = t & 127;

    for (int c = 0; c < 16; c++) {
        int a0 = c * 8;
        ull acc[4] = {0ull, 0ull, 0ull, 0ull};
        #pragma unroll
        for (int k = 0; k < 64; k++) {
            ull wk = packdup(wreg[k]);
            const ull* ap = (const ull*)&at[k][a0];
            ffma2(acc[0], ap[0], wk);
            ffma2(acc[1], ap[1], wk);
            ffma2(acc[2], ap[2], wk);
            ffma2(acc[3], ap[3], wk);
        }
        #pragma unroll
        for (int q = 0; q < 4; q++) {
            float2 v = unpk(acc[q]);
            int a = a0 + 2 * q;
            if (a < aCount)     dst[(size_t)(aBase + a)     * TWOA + j] = v.x + bj;
            if (a + 1 < aCount) dst[(size_t)(aBase + a + 1) * TWOA + j] = v.y + bj;
        }
    }
}

// ---------------- kPack: d_PW -> packed fp16 d_PW16 ----------------
__global__ void __launch_bounds__(256) kPack() {
    int id = blockIdx.x * 256 + threadIdx.x;     // NATOM*32 total
    int a = id >> 5, l = id & 31;
    const float* pw = d_PW + (size_t)a * TWOA;
    float2 va = *(const float2*)(pw + 2 * l);
    float2 vb = *(const float2*)(pw + 64 + 2 * l);
    __half2 hA = __floats2half2_rn(va.x, va.y);
    __half2 hB = __floats2half2_rn(vb.x, vb.y);
    unsigned uA = *(unsigned*)&hA, uB = *(unsigned*)&hB;
    d_PW16[id] = (ull)uA | ((ull)uB << 32);
}

// ---------------- tile fetch (bond raw + neighbor indices) ----------------
__device__ __forceinline__ void fetch_tile(int tile, int t,
                                           float* brawB, int* idxB,
                                           const float* __restrict__ bond,
                                           const int*   __restrict__ nidx) {
    const float* bsrc = bond + (size_t)tile * 96 * BF;
    #pragma unroll
    for (int i = 0; i < 4; i++) {
        int c = t + 256 * i;
        if (c < 96 * BF / 4) cpasync16(brawB + c * 4, bsrc + c * 4);
    }
    if (t < 24) cpasync16(idxB + t * 4, nidx + tile * 96 + t * 4);
}

// ============ persistent kGemmStore: 256 thr = 8 warps x 12 rows x 4 cols ============
// warp w owns atom tile*8+w (rows 12w..12w+11). lane owns cols {2l,2l+1,64+2l,64+2l+1}.
// W3 loaded once/block; bond+idx double-buffered; BN1 stats in regs across tiles.
__global__ void __launch_bounds__(256, 3) kGemmStore(const float* __restrict__ bond,
                                                     const int*   __restrict__ nidx,
                                                     const float* __restrict__ W,
                                                     const float* __restrict__ sc,
                                                     const float* __restrict__ of) {
    extern __shared__ __align__(16) char sm[];
    float* Ws   = (float*)(sm + OFF_WS);
    float* bT   = (float*)(sm + OFF_BT);
    float* braw = (float*)(sm + OFF_BRAW);       // [2][3936]
    int*   idxS = (int*)  (sm + OFF_IDX);        // [2][96]
    __shared__ int sLast;

    int t = threadIdx.x, lane = t & 31, w = t >> 5;   // w in 0..7
    int r0 = 12 * w;
    int cA = 2 * lane;

    // prolog: first tile (group 1), then W3 once (group 2)
    fetch_tile(blockIdx.x, t, braw, idxS, bond, nidx);
    CP_COMMIT();
    {
        const float* wsrc = W + TWOA * TWOA;
        #pragma unroll
        for (int i = 0; i < 6; i++) {
            int c = t + 256 * i;
            if (c < BF * TWOA / 4) cpasync16(Ws + c * 4, wsrc + c * 4);
        }
    }
    CP_COMMIT();

    float ls0 = 0, ls1 = 0, ls2 = 0, ls3 = 0;
    float lq0 = 0, lq1 = 0, lq2 = 0, lq3 = 0;

    int buf = 0;
    for (int tile = blockIdx.x; tile < NT; tile += PBLOCKS) {
        int nxt = tile + PBLOCKS;
        if (nxt < NT) {
            fetch_tile(nxt, t, braw + (buf ^ 1) * 3936, idxS + (buf ^ 1) * 96, bond, nidx);
            CP_COMMIT();
            CP_WAIT(1);          // current tile (and Ws on iter 0) done; next in flight
        } else {
            CP_WAIT(0);
        }
        __syncthreads();

        // transpose braw[buf][r][k] -> bT[k][r]
        const float* brawB = braw + buf * 3936;
        #pragma unroll
        for (int i = 0; i < 16; i++) {
            int id = t + 256 * i;
            if (id < 96 * BF) {
                int k = id / 96, r = id - 96 * k;
                bT[k * BT_PAD + r] = brawB[r * BF + k];
            }
        }
        __syncthreads();

        // GEMM: acc[p] = row-pair (r0+2p, r0+2p+1), 4 cols each (12 rows/warp)
        ull acc[6][4];
        #pragma unroll
        for (int p = 0; p < 6; p++)
            #pragma unroll
            for (int u = 0; u < 4; u++) acc[p][u] = 0ull;

        #pragma unroll
        for (int k = 0; k < BF; k++) {
            float2 wa = *(const float2*)&Ws[k * TWOA + cA];
            float2 wb = *(const float2*)&Ws[k * TWOA + 64 + cA];
            ull w0 = packdup(wa.x), w1 = packdup(wa.y);
            ull w2 = packdup(wb.x), w3 = packdup(wb.y);
            const char* brow = (const char*)(bT + k * BT_PAD + r0);
            ulonglong2 q0 = *(const ulonglong2*)(brow);
            ulonglong2 q1 = *(const ulonglong2*)(brow + 16);
            ulonglong2 q2 = *(const ulonglong2*)(brow + 32);
            ull bv0 = q0.x, bv1 = q0.y, bv2 = q1.x, bv3 = q1.y, bv4 = q2.x, bv5 = q2.y;
            ffma2(acc[0][0], bv0, w0); ffma2(acc[0][1], bv0, w1); ffma2(acc[0][2], bv0, w2); ffma2(acc[0][3], bv0, w3);
            ffma2(acc[1][0], bv1, w0); ffma2(acc[1][1], bv1, w1); ffma2(acc[1][2], bv1, w2); ffma2(acc[1][3], bv1, w3);
            ffma2(acc[2][0], bv2, w0); ffma2(acc[2][1], bv2, w1); ffma2(acc[2][2], bv2, w2); ffma2(acc[2][3], bv2, w3);
            ffma2(acc[3][0], bv3, w0); ffma2(acc[3][1], bv3, w1); ffma2(acc[3][2], bv3, w2); ffma2(acc[3][3], bv3, w3);
            ffma2(acc[4][0], bv4, w0); ffma2(acc[4][1], bv4, w1); ffma2(acc[4][2], bv4, w2); ffma2(acc[4][3], bv4, w3);
            ffma2(acc[5][0], bv5, w0); ffma2(acc[5][1], bv5, w1); ffma2(acc[5][2], bv5, w2); ffma2(acc[5][3], bv5, w3);
        }

        // epilogue: warp owns one atom -> SW via two L2-hit LDGs; PW16 gathers; fp16 store
        int atomId = tile * 8 + w;
        float2 swA = __ldg((const float2*)(d_SW + (size_t)atomId * TWOA + cA));
        float2 swB = __ldg((const float2*)(d_SW + (size_t)atomId * TWOA + 64 + cA));
        const int* idB = idxS + buf * 96 + r0;
        ull* gbase = d_gated16 + (size_t)(tile * 96 + r0) * 32;

        #pragma unroll
        for (int p = 0; p < 6; p++) {
            float2 aA0 = unpk(acc[p][0]), aA1 = unpk(acc[p][1]);
            float2 aB0 = unpk(acc[p][2]), aB1 = unpk(acc[p][3]);
            #pragma unroll
            for (int s = 0; s < 2; s++) {
                int rr = 2 * p + s;               // row within warp, 0..11
                ull pk = __ldg(d_PW16 + (size_t)idB[rr] * 32 + lane);
                unsigned plo = (unsigned)pk, phi = (unsigned)(pk >> 32);
                float2 pA = __half22float2(*(__half2*)&plo);
                float2 pB = __half22float2(*(__half2*)&phi);
                float v0 = (s ? aA0.y : aA0.x) + swA.x + pA.x;
                float v1 = (s ? aA1.y : aA1.x) + swA.y + pA.y;
                float v2 = (s ? aB0.y : aB0.x) + swB.x + pB.x;
                float v3 = (s ? aB1.y : aB1.x) + swB.y + pB.y;
                __half2 hA = __floats2half2_rn(v0, v1);
                __half2 hB = __floats2half2_rn(v2, v3);
                unsigned uA = *(unsigned*)&hA, uB = *(unsigned*)&hB;
                __stcs(gbase + (size_t)rr * 32 + lane, (ull)uA | ((ull)uB << 32));
                ls0 += v0; lq0 += v0 * v0;
                ls1 += v1; lq1 += v1 * v1;
                ls2 += v2; lq2 += v2 * v2;
                ls3 += v3; lq3 += v3 * v3;
            }
        }
        __syncthreads();     // k-loop/epilogue reads done before next transpose/fetch reuse
        buf ^= 1;
    }

    // one stats reduction + atomic round per block (overlay braw region)
    float* redS = (float*)(sm + OFF_RED);
    float* redQ = redS + 8 * TWOA;
    redS[w * TWOA + cA] = ls0;       redS[w * TWOA + cA + 1] = ls1;
    redS[w * TWOA + 64 + cA] = ls2;  redS[w * TWOA + 64 + cA + 1] = ls3;
    redQ[w * TWOA + cA] = lq0;       redQ[w * TWOA + cA + 1] = lq1;
    redQ[w * TWOA + 64 + cA] = lq2;  redQ[w * TWOA + 64 + cA + 1] = lq3;
    __syncthreads();
    if (t < TWOA) {
        float s = 0.0f, q = 0.0f;
        #pragma unroll
        for (int w2 = 0; w2 < 8; w2++) { s += redS[w2 * TWOA + t]; q += redQ[w2 * TWOA + t]; }
        atomicAdd(&d_s1[t], (double)s);
        atomicAdd(&d_q1[t], (double)q);
    }
    __syncthreads();
    if (t == 0) {
        __threadfence();
        unsigned old = atomicAdd(&d_c1, 1u);
        sLast = (old == PBLOCKS - 1) ? 1 : 0;
    }
    __syncthreads();
    if (sLast && t < TWOA) {
        double s = *((volatile double*)&d_s1[t]);
        double q = *((volatile double*)&d_q1[t]);
        double mean = s / NMF;
        double var  = q / NMF - mean * mean;
        float g = sc[t] * (float)(1.0 / sqrt(var + EPSBN));
        d_g1[t] = g;
        d_h1[t] = of[t] - (float)mean * g;
    }
}

// ---------------- kC: 4 atoms/warp, 32 atoms/block; LDG.128 half-warp row split ----------------
__global__ void __launch_bounds__(256) kC(const float* __restrict__ sc,
                                          const float* __restrict__ of) {
    __shared__ float rs[32][AF];
    __shared__ float rq[32][AF];
    __shared__ int sLast;
    int t = threadIdx.x;
    int lane = t & 31, w = t >> 5;
    int half = lane >> 4, q = lane & 15;
    int c0 = 4 * q;

    float4 G1A = *(const float4*)&d_g1[c0];
    float4 H1A = *(const float4*)&d_h1[c0];
    float4 G1B = *(const float4*)&d_g1[64 + c0];
    float4 H1B = *(const float4*)&d_h1[64 + c0];

    int aBase = blockIdx.x * 32 + w * 4;
    #pragma unroll
    for (int u = 0; u < 4; u++) {
        int a = aBase + u;
        const uint4* gp = (const uint4*)(d_gated16 + (size_t)a * MNBR * 32);
        float s0 = 0.0f, s1 = 0.0f, s2 = 0.0f, s3 = 0.0f;
        #pragma unroll
        for (int i = 0; i < 6; i++) {
            int m = 2 * i + half;
            uint4 v = __ldcs(gp + m * 16 + q);
            float2 f01 = __half22float2(*(__half2*)&v.x);
            float2 c01 = __half22float2(*(__half2*)&v.y);
            float2 f23 = __half22float2(*(__half2*)&v.z);
            float2 c23 = __half22float2(*(__half2*)&v.w);
            float xf0 = f01.x * G1A.x + H1A.x;
            float xf1 = f01.y * G1A.y + H1A.y;
            float xf2 = f23.x * G1A.z + H1A.z;
            float xf3 = f23.y * G1A.w + H1A.w;
            float xc0 = c01.x * G1B.x + H1B.x;
            float xc1 = c01.y * G1B.y + H1B.y;
            float xc2 = c23.x * G1B.z + H1B.z;
            float xc3 = c23.y * G1B.w + H1B.w;
            s0 += sigmoidf_(xf0) * softplusf_(xc0);
            s1 += sigmoidf_(xf1) * softplusf_(xc1);
            s2 += sigmoidf_(xf2) * softplusf_(xc2);
            s3 += sigmoidf_(xf3) * softplusf_(xc3);
        }
        s0 += __shfl_xor_sync(0xffffffffu, s0, 16);
        s1 += __shfl_xor_sync(0xffffffffu, s1, 16);
        s2 += __shfl_xor_sync(0xffffffffu, s2, 16);
        s3 += __shfl_xor_sync(0xffffffffu, s3, 16);
        if (half == 0) {
            float4 sv; sv.x = s0; sv.y = s1; sv.z = s2; sv.w = s3;
            *(float4*)&d_summed[(size_t)a * AF + c0] = sv;
            *(float4*)&rs[w * 4 + u][c0] = sv;
            float4 qv; qv.x = s0 * s0; qv.y = s1 * s1; qv.z = s2 * s2; qv.w = s3 * s3;
            *(float4*)&rq[w * 4 + u][c0] = qv;
        }
    }
    __syncthreads();
    if (t < AF) {
        float s = 0.0f, qq = 0.0f;
        #pragma unroll
        for (int r = 0; r < 32; r++) { s += rs[r][t]; qq += rq[r][t]; }
        atomicAdd(&d_s2[t], (double)s);
        atomicAdd(&d_q2[t], (double)qq);
    }
    __syncthreads();
    if (t == 0) {
        __threadfence();
        unsigned old = atomicAdd(&d_c2, 1u);
        sLast = (old == NATOM / 32 - 1) ? 1 : 0;
    }
    __syncthreads();
    if (sLast && t < AF) {
        double s = *((volatile double*)&d_s2[t]);
        double qq = *((volatile double*)&d_q2[t]);
        double mean = s / NF;
        double var  = qq / NF - mean * mean;
        float g = sc[t] * (float)(1.0 / sqrt(var + EPSBN));
        d_g2[t] = g;
        d_h2[t] = of[t] - (float)mean * g;
    }
}

// ---------------- kD: out = softplus(atom + BN2(summed)) ----------------
__global__ void __launch_bounds__(256) kD(const float* __restrict__ atom,
                                          float* __restrict__ out) {
    int i = blockIdx.x * 256 + threadIdx.x;
    int c = i & (AF - 1);
    float y = d_summed[i] * d_g2[c] + d_h2[c];
    out[i] = softplusf_(atom[i] + y);
}

// ---------------- launch ----------------
extern "C" void kernel_launch(void* const* d_in, const int* in_sizes, int n_in,
                              void* d_out, int out_size) {
    const int*   nidx = (const int*)  d_in[0];
    const float* atom = (const float*)d_in[1];
    const float* bond = (const float*)d_in[2];
    const float* W    = (const float*)d_in[3];
    const float* bias = (const float*)d_in[4];
    const float* bn1s = (const float*)d_in[5];
    const float* bn1o = (const float*)d_in[6];
    const float* bn2s = (const float*)d_in[7];
    const float* bn2o = (const float*)d_in[8];
    float* out = (float*)d_out;

    cudaFuncSetAttribute(kGemmStore, cudaFuncAttributeMaxDynamicSharedMemorySize, SMEM_BYTES);

    kInit<<<1, 128>>>();                                                     // slot 1
    kA<<<(NATOM + 127) / 128, 256>>>(atom, W, bias);                         // slot 2
    kPack<<<(NATOM * 32) / 256, 256>>>();                                    // slot 3
    kGemmStore<<<PBLOCKS, 256, SMEM_BYTES>>>(bond, nidx, W, bn1s, bn1o);     // slot 4 (ncu)
    kC<<<NATOM / 32, 256>>>(bn2s, bn2o);                                     // slot 5
    kD<<<(NATOM * AF) / 256, 256>>>(atom, out);                              // slot 6
}

// round 13
// speedup vs baseline: 1.0487x; 1.0487x over previous
#include <cuda_runtime.h>
#include <cuda_fp16.h>

#define NATOM 100000
#define MNBR  12
#define AF    64
#define BF    41
#define TWOA  128
#define NM    (NATOM*MNBR)          // 1200000
#define NMF   ((double)NM)
#define NF    ((double)NATOM)
#define EPSBN 1e-5
#define NT    (NM/96)               // 12500 tiles
#define PBLOCKS 296                 // persistent GEMM: 2 blocks/SM x 148 SMs
#define NTC    (NATOM/32)           // 3125 kC tiles
#define PB_C   592                  // persistent kC: 4 blocks/SM x 148 SMs

// ---- dynamic smem layout (bytes) for persistent kGemmStore (R10 proven shape) ----
#define BT_PAD    104
#define OFF_WS    0                              // float Ws[41*128]        = 20992
#define OFF_BT    20992                          // float bT[41*104]        = 17056
#define OFF_BRAW  38048                          // float braw[2][3936]     = 31488
#define OFF_SWS   69536                          // float SWs[2][1024]      = 8192
#define OFF_IDX   77728                          // int   idxS[2][96]       = 768
#define OFF_RED   78496                          // float red[2][12*128]    = 12288
#define SMEM_BYTES 90784                         // x2 blocks = 181.6 KB

typedef unsigned long long ull;

// ---------------- scratch (device globals; no allocations) ----------------
__device__ float  d_SW[(size_t)NATOM*TWOA];      // atom @ W[0:64] + bias
__device__ float  d_PW[(size_t)NATOM*TWOA];      // atom @ W[64:128] (fp32)
__device__ ull    d_PW16[(size_t)NATOM*32];      // packed fp16 PW: lane l = {2l,2l+1,64+2l,64+2l+1}
__device__ ull    d_gated16[(size_t)NM*32];      // fp16 gated, same packing (307 MB)
__device__ float  d_summed[(size_t)NATOM*AF];
__device__ double d_s1[TWOA], d_q1[TWOA];
__device__ double d_s2[AF],   d_q2[AF];
__device__ float  d_g1[TWOA], d_h1[TWOA];
__device__ float  d_g2[AF],   d_h2[AF];
__device__ unsigned d_c1, d_c2;

// ---------------- helpers ----------------
__device__ __forceinline__ void ffma2(ull &d, ull a, ull b) {
    asm("fma.rn.f32x2 %0, %1, %2, %0;" : "+l"(d) : "l"(a), "l"(b));
}
__device__ __forceinline__ ull packdup(float x) {
    ull r; asm("mov.b64 %0, {%1, %1};" : "=l"(r) : "f"(x)); return r;
}
__device__ __forceinline__ float2 unpk(ull v) {
    float2 r; asm("mov.b64 {%0, %1}, %2;" : "=f"(r.x), "=f"(r.y) : "l"(v)); return r;
}
__device__ __forceinline__ float sigmoidf_(float x) {
    return __fdividef(1.0f, 1.0f + __expf(-x));
}
__device__ __forceinline__ float softplusf_(float x) {
    float e = __expf(-fabsf(x));
    return fmaxf(x, 0.0f) + __logf(1.0f + e);
}
__device__ __forceinline__ void cpasync16(void* dst_smem, const void* src) {
    unsigned s = (unsigned)__cvta_generic_to_shared(dst_smem);
    asm volatile("cp.async.cg.shared.global [%0], [%1], 16;" :: "r"(s), "l"(src) : "memory");
}
#define CP_COMMIT() asm volatile("cp.async.commit_group;" ::: "memory")
#define CP_WAIT(n)  asm volatile("cp.async.wait_group %0;" :: "n"(n) : "memory")

// ---------------- kInit ----------------
__global__ void kInit() {
    int t = threadIdx.x;
    if (t < TWOA) { d_s1[t] = 0.0; d_q1[t] = 0.0; }
    if (t < AF)   { d_s2[t] = 0.0; d_q2[t] = 0.0; }
    if (t == 0)   { d_c1 = 0u; d_c2 = 0u; }
}

// ---------------- kA: SW = atom@W1 + b, PW = atom@W2 ----------------
__global__ void __launch_bounds__(256) kA(const float* __restrict__ atom,
                                          const float* __restrict__ W,
                                          const float* __restrict__ bias) {
    __shared__ __align__(16) float at[64][132];
    int t = threadIdx.x;
    int aBase = blockIdx.x * 128;
    int aCount = NATOM - aBase; if (aCount > 128) aCount = 128;

    float wreg[64];
    const float* wp = (t < 128) ? (W + t) : (W + 64 * TWOA + (t - 128));
    #pragma unroll
    for (int k = 0; k < 64; k++) wreg[k] = wp[k * TWOA];
    float bj = (t < 128) ? bias[t] : 0.0f;

    for (int idx = t; idx < 128 * 64; idx += 256) {
        int a = idx >> 6, k = idx & 63;
        at[k][a] = (a < aCount) ? atom[(size_t)(aBase + a) * AF + k] : 0.0f;
    }
    __syncthreads();

    float* dst = (t < 128) ? d_SW : d_PW;
    int j = t & 127;

    for (int c = 0; c < 16; c++) {
        int a0 = c * 8;
        ull acc[4] = {0ull, 0ull, 0ull, 0ull};
        #pragma unroll
        for (int k = 0; k < 64; k++) {
            ull wk = packdup(wreg[k]);
            const ull* ap = (const ull*)&at[k][a0];
            ffma2(acc[0], ap[0], wk);
            ffma2(acc[1], ap[1], wk);
            ffma2(acc[2], ap[2], wk);
            ffma2(acc[3], ap[3], wk);
        }
        #pragma unroll
        for (int q = 0; q < 4; q++) {
            float2 v = unpk(acc[q]);
            int a = a0 + 2 * q;
            if (a < aCount)     dst[(size_t)(aBase + a)     * TWOA + j] = v.x + bj;
            if (a + 1 < aCount) dst[(size_t)(aBase + a + 1) * TWOA + j] = v.y + bj;
        }
    }
}

// ---------------- kPack: d_PW -> packed fp16 d_PW16 ----------------
__global__ void __launch_bounds__(256) kPack() {
    int id = blockIdx.x * 256 + threadIdx.x;     // NATOM*32 total
    int a = id >> 5, l = id & 31;
    const float* pw = d_PW + (size_t)a * TWOA;
    float2 va = *(const float2*)(pw + 2 * l);
    float2 vb = *(const float2*)(pw + 64 + 2 * l);
    __half2 hA = __floats2half2_rn(va.x, va.y);
    __half2 hB = __floats2half2_rn(vb.x, vb.y);
    unsigned uA = *(unsigned*)&hA, uB = *(unsigned*)&hB;
    d_PW16[id] = (ull)uA | ((ull)uB << 32);
}

// ---------------- tile fetch (bond raw + SW rows + neighbor indices) ----------------
__device__ __forceinline__ void fetch_tile(int tile, int t,
                                           float* brawB, float* SWsB, int* idxB,
                                           const float* __restrict__ bond,
                                           const int*   __restrict__ nidx) {
    const float* bsrc = bond + (size_t)tile * 96 * BF;
    #pragma unroll
    for (int i = 0; i < 3; i++) {
        int c = t + 384 * i;
        if (c < 96 * BF / 4) cpasync16(brawB + c * 4, bsrc + c * 4);
    }
    if (t < 256) cpasync16(SWsB + t * 4, d_SW + (size_t)tile * 8 * TWOA + t * 4);
    if (t < 24)  cpasync16(idxB + t * 4, nidx + tile * 96 + t * 4);
}

// ============ persistent kGemmStore (R10 proven): 384 thr = 12 warps x 8 rows ============
__global__ void __launch_bounds__(384, 2) kGemmStore(const float* __restrict__ bond,
                                                     const int*   __restrict__ nidx,
                                                     const float* __restrict__ W,
                                                     const float* __restrict__ sc,
                                                     const float* __restrict__ of) {
    extern __shared__ __align__(16) char sm[];
    float* Ws   = (float*)(sm + OFF_WS);
    float* bT   = (float*)(sm + OFF_BT);
    float* braw = (float*)(sm + OFF_BRAW);       // [2][3936]
    float* SWs  = (float*)(sm + OFF_SWS);        // [2][1024]
    int*   idxS = (int*)  (sm + OFF_IDX);        // [2][96]
    __shared__ int sLast;

    int t = threadIdx.x, lane = t & 31, w = t >> 5;   // w in 0..11
    int r0 = 8 * w;
    int cA = 2 * lane;

    fetch_tile(blockIdx.x, t, braw, SWs, idxS, bond, nidx);
    CP_COMMIT();
    {
        const float* wsrc = W + TWOA * TWOA;
        #pragma unroll
        for (int i = 0; i < 4; i++) {
            int c = t + 384 * i;
            if (c < BF * TWOA / 4) cpasync16(Ws + c * 4, wsrc + c * 4);
        }
    }
    CP_COMMIT();

    float ls0 = 0, ls1 = 0, ls2 = 0, ls3 = 0;
    float lq0 = 0, lq1 = 0, lq2 = 0, lq3 = 0;

    int buf = 0;
    for (int tile = blockIdx.x; tile < NT; tile += PBLOCKS) {
        int nxt = tile + PBLOCKS;
        if (nxt < NT) {
            fetch_tile(nxt, t, braw + (buf ^ 1) * 3936, SWs + (buf ^ 1) * 1024,
                       idxS + (buf ^ 1) * 96, bond, nidx);
            CP_COMMIT();
            CP_WAIT(1);
        } else {
            CP_WAIT(0);
        }
        __syncthreads();

        const float* brawB = braw + buf * 3936;
        #pragma unroll
        for (int i = 0; i < 11; i++) {
            int id = t + 384 * i;
            if (id < 96 * BF) {
                int k = id / 96, r = id - 96 * k;
                bT[k * BT_PAD + r] = brawB[r * BF + k];
            }
        }
        __syncthreads();

        ull acc[4][4];
        #pragma unroll
        for (int p = 0; p < 4; p++)
            #pragma unroll
            for (int u = 0; u < 4; u++) acc[p][u] = 0ull;

        #pragma unroll
        for (int k = 0; k < BF; k++) {
            float2 wa = *(const float2*)&Ws[k * TWOA + cA];
            float2 wb = *(const float2*)&Ws[k * TWOA + 64 + cA];
            ull w0 = packdup(wa.x), w1 = packdup(wa.y);
            ull w2 = packdup(wb.x), w3 = packdup(wb.y);
            const char* brow = (const char*)(bT + k * BT_PAD + r0);
            ulonglong2 q0 = *(const ulonglong2*)(brow);
            ulonglong2 q1 = *(const ulonglong2*)(brow + 16);
            ull bv0 = q0.x, bv1 = q0.y, bv2 = q1.x, bv3 = q1.y;
            ffma2(acc[0][0], bv0, w0); ffma2(acc[0][1], bv0, w1); ffma2(acc[0][2], bv0, w2); ffma2(acc[0][3], bv0, w3);
            ffma2(acc[1][0], bv1, w0); ffma2(acc[1][1], bv1, w1); ffma2(acc[1][2], bv1, w2); ffma2(acc[1][3], bv1, w3);
            ffma2(acc[2][0], bv2, w0); ffma2(acc[2][1], bv2, w1); ffma2(acc[2][2], bv2, w2); ffma2(acc[2][3], bv2, w3);
            ffma2(acc[3][0], bv3, w0); ffma2(acc[3][1], bv3, w1); ffma2(acc[3][2], bv3, w2); ffma2(acc[3][3], bv3, w3);
        }

        const float* SWb = SWs + buf * 1024;
        const int*   idB = idxS + buf * 96;
        ull* gbase = d_gated16 + (size_t)(tile * 96 + r0) * 32;

        #pragma unroll
        for (int p = 0; p < 4; p++) {
            float2 aA0 = unpk(acc[p][0]), aA1 = unpk(acc[p][1]);
            float2 aB0 = unpk(acc[p][2]), aB1 = unpk(acc[p][3]);
            #pragma unroll
            for (int s = 0; s < 2; s++) {
                int rr = r0 + 2 * p + s;          // local row 0..95
                int aLoc = rr / 12;               // local atom 0..7
                const float* swr = SWb + aLoc * TWOA;
                ull pk = __ldg(d_PW16 + (size_t)idB[rr] * 32 + lane);
                unsigned plo = (unsigned)pk, phi = (unsigned)(pk >> 32);
                float2 pA = __half22float2(*(__half2*)&plo);
                float2 pB = __half22float2(*(__half2*)&phi);
                float2 swA = *(const float2*)(swr + cA);
                float2 swB = *(const float2*)(swr + 64 + cA);
                float v0 = (s ? aA0.y : aA0.x) + swA.x + pA.x;
                float v1 = (s ? aA1.y : aA1.x) + swA.y + pA.y;
                float v2 = (s ? aB0.y : aB0.x) + swB.x + pB.x;
                float v3 = (s ? aB1.y : aB1.x) + swB.y + pB.y;
                __half2 hA = __floats2half2_rn(v0, v1);
                __half2 hB = __floats2half2_rn(v2, v3);
                unsigned uA = *(unsigned*)&hA, uB = *(unsigned*)&hB;
                __stcs(gbase + (size_t)(2 * p + s) * 32 + lane, (ull)uA | ((ull)uB << 32));
                ls0 += v0; lq0 += v0 * v0;
                ls1 += v1; lq1 += v1 * v1;
                ls2 += v2; lq2 += v2 * v2;
                ls3 += v3; lq3 += v3 * v3;
            }
        }
        __syncthreads();
        buf ^= 1;
    }

    float* redS = (float*)(sm + OFF_RED);
    float* redQ = redS + 12 * TWOA;
    redS[w * TWOA + cA] = ls0;       redS[w * TWOA + cA + 1] = ls1;
    redS[w * TWOA + 64 + cA] = ls2;  redS[w * TWOA + 64 + cA + 1] = ls3;
    redQ[w * TWOA + cA] = lq0;       redQ[w * TWOA + cA + 1] = lq1;
    redQ[w * TWOA + 64 + cA] = lq2;  redQ[w * TWOA + 64 + cA + 1] = lq3;
    __syncthreads();
    if (t < TWOA) {
        float s = 0.0f, q = 0.0f;
        #pragma unroll
        for (int w2 = 0; w2 < 12; w2++) { s += redS[w2 * TWOA + t]; q += redQ[w2 * TWOA + t]; }
        atomicAdd(&d_s1[t], (double)s);
        atomicAdd(&d_q1[t], (double)q);
    }
    __syncthreads();
    if (t == 0) {
        __threadfence();
        unsigned old = atomicAdd(&d_c1, 1u);
        sLast = (old == PBLOCKS - 1) ? 1 : 0;
    }
    __syncthreads();
    if (sLast && t < TWOA) {
        double s = *((volatile double*)&d_s1[t]);
        double q = *((volatile double*)&d_q1[t]);
        double mean = s / NMF;
        double var  = q / NMF - mean * mean;
        float g = sc[t] * (float)(1.0 / sqrt(var + EPSBN));
        d_g1[t] = g;
        d_h1[t] = of[t] - (float)mean * g;
    }
}

// ---------------- kC: persistent; 4 atoms/warp/tile; BN2 stats in regs across tiles ----------
__global__ void __launch_bounds__(256) kC(const float* __restrict__ sc,
                                          const float* __restrict__ of) {
    __shared__ float rs[8][AF];
    __shared__ float rq[8][AF];
    __shared__ int sLast;
    int t = threadIdx.x;
    int lane = t & 31, w = t >> 5;
    int half = lane >> 4, q = lane & 15;
    int c0 = 4 * q;

    float4 G1A = *(const float4*)&d_g1[c0];
    float4 H1A = *(const float4*)&d_h1[c0];
    float4 G1B = *(const float4*)&d_g1[64 + c0];
    float4 H1B = *(const float4*)&d_h1[64 + c0];

    float as0 = 0, as1 = 0, as2 = 0, as3 = 0;   // Σs per column (half==0 lanes)
    float aq0 = 0, aq1 = 0, aq2 = 0, aq3 = 0;   // Σs² per column

    for (int tb = blockIdx.x; tb < NTC; tb += PB_C) {
        int aBase = tb * 32 + w * 4;
        #pragma unroll
        for (int u = 0; u < 4; u++) {
            int a = aBase + u;
            const uint4* gp = (const uint4*)(d_gated16 + (size_t)a * MNBR * 32);
            float s0 = 0.0f, s1 = 0.0f, s2 = 0.0f, s3 = 0.0f;
            #pragma unroll
            for (int i = 0; i < 6; i++) {
                int m = 2 * i + half;
                uint4 v = __ldcs(gp + m * 16 + q);
                float2 f01 = __half22float2(*(__half2*)&v.x);
                float2 c01 = __half22float2(*(__half2*)&v.y);
                float2 f23 = __half22float2(*(__half2*)&v.z);
                float2 c23 = __half22float2(*(__half2*)&v.w);
                float xf0 = f01.x * G1A.x + H1A.x;
                float xf1 = f01.y * G1A.y + H1A.y;
                float xf2 = f23.x * G1A.z + H1A.z;
                float xf3 = f23.y * G1A.w + H1A.w;
                float xc0 = c01.x * G1B.x + H1B.x;
                float xc1 = c01.y * G1B.y + H1B.y;
                float xc2 = c23.x * G1B.z + H1B.z;
                float xc3 = c23.y * G1B.w + H1B.w;
                s0 += sigmoidf_(xf0) * softplusf_(xc0);
                s1 += sigmoidf_(xf1) * softplusf_(xc1);
                s2 += sigmoidf_(xf2) * softplusf_(xc2);
                s3 += sigmoidf_(xf3) * softplusf_(xc3);
            }
            s0 += __shfl_xor_sync(0xffffffffu, s0, 16);
            s1 += __shfl_xor_sync(0xffffffffu, s1, 16);
            s2 += __shfl_xor_sync(0xffffffffu, s2, 16);
            s3 += __shfl_xor_sync(0xffffffffu, s3, 16);
            if (half == 0) {
                float4 sv; sv.x = s0; sv.y = s1; sv.z = s2; sv.w = s3;
                *(float4*)&d_summed[(size_t)a * AF + c0] = sv;
                as0 += s0; aq0 += s0 * s0;
                as1 += s1; aq1 += s1 * s1;
                as2 += s2; aq2 += s2 * s2;
                as3 += s3; aq3 += s3 * s3;
            }
        }
    }

    // once-per-block reduction
    if (half == 0) {
        float4 sv; sv.x = as0; sv.y = as1; sv.z = as2; sv.w = as3;
        *(float4*)&rs[w][c0] = sv;
        float4 qv; qv.x = aq0; qv.y = aq1; qv.z = aq2; qv.w = aq3;
        *(float4*)&rq[w][c0] = qv;
    }
    __syncthreads();
    if (t < AF) {
        float s = 0.0f, qq = 0.0f;
        #pragma unroll
        for (int r = 0; r < 8; r++) { s += rs[r][t]; qq += rq[r][t]; }
        atomicAdd(&d_s2[t], (double)s);
        atomicAdd(&d_q2[t], (double)qq);
    }
    __syncthreads();
    if (t == 0) {
        __threadfence();
        unsigned old = atomicAdd(&d_c2, 1u);
        sLast = (old == PB_C - 1) ? 1 : 0;
    }
    __syncthreads();
    if (sLast && t < AF) {
        double s = *((volatile double*)&d_s2[t]);
        double qq = *((volatile double*)&d_q2[t]);
        double mean = s / NF;
        double var  = qq / NF - mean * mean;
        float g = sc[t] * (float)(1.0 / sqrt(var + EPSBN));
        d_g2[t] = g;
        d_h2[t] = of[t] - (float)mean * g;
    }
}

// ---------------- kD: out = softplus(atom + BN2(summed)) ----------------
__global__ void __launch_bounds__(256) kD(const float* __restrict__ atom,
                                          float* __restrict__ out) {
    int i = blockIdx.x * 256 + threadIdx.x;
    int c = i & (AF - 1);
    float y = d_summed[i] * d_g2[c] + d_h2[c];
    out[i] = softplusf_(atom[i] + y);
}

// ---------------- launch ----------------
extern "C" void kernel_launch(void* const* d_in, const int* in_sizes, int n_in,
                              void* d_out, int out_size) {
    const int*   nidx = (const int*)  d_in[0];
    const float* atom = (const float*)d_in[1];
    const float* bond = (const float*)d_in[2];
    const float* W    = (const float*)d_in[3];
    const float* bias = (const float*)d_in[4];
    const float* bn1s = (const float*)d_in[5];
    const float* bn1o = (const float*)d_in[6];
    const float* bn2s = (const float*)d_in[7];
    const float* bn2o = (const float*)d_in[8];
    float* out = (float*)d_out;

    cudaFuncSetAttribute(kGemmStore, cudaFuncAttributeMaxDynamicSharedMemorySize, SMEM_BYTES);

    kInit<<<1, 128>>>();                                                     // slot 1
    kA<<<(NATOM + 127) / 128, 256>>>(atom, W, bias);                         // slot 2
    kPack<<<(NATOM * 32) / 256, 256>>>();                                    // slot 3
    kGemmStore<<<PBLOCKS, 384, SMEM_BYTES>>>(bond, nidx, W, bn1s, bn1o);     // slot 4 (ncu)
    kC<<<PB_C, 256>>>(bn2s, bn2o);                                           // slot 5
    kD<<<(NATOM * AF) / 256, 256>>>(atom, out);                              // slot 6
}

// round 14
// speedup vs baseline: 1.0524x; 1.0035x over previous
#include <cuda_runtime.h>
#include <cuda_fp16.h>

#define NATOM 100000
#define MNBR  12
#define AF    64
#define BF    41
#define TWOA  128
#define NM    (NATOM*MNBR)          // 1200000
#define NMF   ((double)NM)
#define NF    ((double)NATOM)
#define EPSBN 1e-5
#define NT    (NM/96)               // 12500 tiles
#define PBLOCKS 296                 // persistent GEMM: 2 blocks/SM x 148 SMs
#define NTC    (NATOM/32)           // 3125 kC tiles
#define PB_C   592                  // persistent kC: 4 blocks/SM x 148 SMs

// ---- dynamic smem layout (bytes) for persistent kGemmStore ----
#define BT_PAD    104
#define OFF_WS    0                              // float Ws[41*128]        = 20992
#define OFF_BT    20992                          // float bT[41*104]        = 17056
#define OFF_BRAW  38048                          // float braw[3936]        = 15744 (single buf)
#define OFF_SWS   53792                          // float SWs[2][1024]      = 8192
#define OFF_PWS   61984                          // ull   PWs[2][96*32]     = 49152
#define OFF_IDX   111136                         // int   idxS[3][96]       = 1152
#define SMEM_BYTES 112288                        // x2 blocks = 224.6 KB (<= 228 KB)
#define OFF_RED   OFF_BRAW                       // red 12*128*2*4 = 12288 <= 15744 (overlay)

typedef unsigned long long ull;

// ---------------- scratch (device globals; no allocations) ----------------
__device__ float  d_SW[(size_t)NATOM*TWOA];      // atom @ W[0:64] + bias
__device__ float  d_PW[(size_t)NATOM*TWOA];      // atom @ W[64:128] (fp32)
__device__ ull    d_PW16[(size_t)NATOM*32];      // packed fp16 PW: lane l = {2l,2l+1,64+2l,64+2l+1}
__device__ ull    d_gated16[(size_t)NM*32];      // fp16 gated, same packing (307 MB)
__device__ float  d_summed[(size_t)NATOM*AF];
__device__ double d_s1[TWOA], d_q1[TWOA];
__device__ double d_s2[AF],   d_q2[AF];
__device__ float  d_g1[TWOA], d_h1[TWOA];
__device__ float  d_g2[AF],   d_h2[AF];
__device__ unsigned d_c1, d_c2;

// ---------------- helpers ----------------
__device__ __forceinline__ void ffma2(ull &d, ull a, ull b) {
    asm("fma.rn.f32x2 %0, %1, %2, %0;" : "+l"(d) : "l"(a), "l"(b));
}
__device__ __forceinline__ ull packdup(float x) {
    ull r; asm("mov.b64 %0, {%1, %1};" : "=l"(r) : "f"(x)); return r;
}
__device__ __forceinline__ float2 unpk(ull v) {
    float2 r; asm("mov.b64 {%0, %1}, %2;" : "=f"(r.x), "=f"(r.y) : "l"(v)); return r;
}
__device__ __forceinline__ float sigmoidf_(float x) {
    return __fdividef(1.0f, 1.0f + __expf(-x));
}
__device__ __forceinline__ float softplusf_(float x) {
    float e = __expf(-fabsf(x));
    return fmaxf(x, 0.0f) + __logf(1.0f + e);
}
__device__ __forceinline__ void cpasync16(void* dst_smem, const void* src) {
    unsigned s = (unsigned)__cvta_generic_to_shared(dst_smem);
    asm volatile("cp.async.cg.shared.global [%0], [%1], 16;" :: "r"(s), "l"(src) : "memory");
}
#define CP_COMMIT() asm volatile("cp.async.commit_group;" ::: "memory")
#define CP_WAIT(n)  asm volatile("cp.async.wait_group %0;" :: "n"(n) : "memory")

// ---------------- kInit ----------------
__global__ void kInit() {
    int t = threadIdx.x;
    if (t < TWOA) { d_s1[t] = 0.0; d_q1[t] = 0.0; }
    if (t < AF)   { d_s2[t] = 0.0; d_q2[t] = 0.0; }
    if (t == 0)   { d_c1 = 0u; d_c2 = 0u; }
}

// ---------------- kA: SW = atom@W1 + b, PW = atom@W2 ----------------
__global__ void __launch_bounds__(256) kA(const float* __restrict__ atom,
                                          const float* __restrict__ W,
                                          const float* __restrict__ bias) {
    __shared__ __align__(16) float at[64][132];
    int t = threadIdx.x;
    int aBase = blockIdx.x * 128;
    int aCount = NATOM - aBase; if (aCount > 128) aCount = 128;

    float wreg[64];
    const float* wp = (t < 128) ? (W + t) : (W + 64 * TWOA + (t - 128));
    #pragma unroll
    for (int k = 0; k < 64; k++) wreg[k] = wp[k * TWOA];
    float bj = (t < 128) ? bias[t] : 0.0f;

    for (int idx = t; idx < 128 * 64; idx += 256) {
        int a = idx >> 6, k = idx & 63;
        at[k][a] = (a < aCount) ? atom[(size_t)(aBase + a) * AF + k] : 0.0f;
    }
    __syncthreads();

    float* dst = (t < 128) ? d_SW : d_PW;
    int j = t & 127;

    for (int c = 0; c < 16; c++) {
        int a0 = c * 8;
        ull acc[4] = {0ull, 0ull, 0ull, 0ull};
        #pragma unroll
        for (int k = 0; k < 64; k++) {
            ull wk = packdup(wreg[k]);
            const ull* ap = (const ull*)&at[k][a0];
            ffma2(acc[0], ap[0], wk);
            ffma2(acc[1], ap[1], wk);
            ffma2(acc[2], ap[2], wk);
            ffma2(acc[3], ap[3], wk);
        }
        #pragma unroll
        for (int q = 0; q < 4; q++) {
            float2 v = unpk(acc[q]);
            int a = a0 + 2 * q;
            if (a < aCount)     dst[(size_t)(aBase + a)     * TWOA + j] = v.x + bj;
            if (a + 1 < aCount) dst[(size_t)(aBase + a + 1) * TWOA + j] = v.y + bj;
        }
    }
}

// ---------------- kPack: d_PW -> packed fp16 d_PW16 ----------------
__global__ void __launch_bounds__(256) kPack() {
    int id = blockIdx.x * 256 + threadIdx.x;     // NATOM*32 total
    int a = id >> 5, l = id & 31;
    const float* pw = d_PW + (size_t)a * TWOA;
    float2 va = *(const float2*)(pw + 2 * l);
    float2 vb = *(const float2*)(pw + 64 + 2 * l);
    __half2 hA = __floats2half2_rn(va.x, va.y);
    __half2 hB = __floats2half2_rn(vb.x, vb.y);
    unsigned uA = *(unsigned*)&hA, uB = *(unsigned*)&hB;
    d_PW16[id] = (ull)uA | ((ull)uB << 32);
}

// ============ persistent kGemmStore: 384 thr = 12 warps x 8 rows; PW gathered via cp.async ====
__global__ void __launch_bounds__(384, 2) kGemmStore(const float* __restrict__ bond,
                                                     const int*   __restrict__ nidx,
                                                     const float* __restrict__ W,
                                                     const float* __restrict__ sc,
                                                     const float* __restrict__ of) {
    extern __shared__ __align__(16) char sm[];
    float* Ws   = (float*)(sm + OFF_WS);
    float* bT   = (float*)(sm + OFF_BT);
    float* braw = (float*)(sm + OFF_BRAW);       // single buffer
    float* SWs  = (float*)(sm + OFF_SWS);        // [2][1024]
    ull*   PWs  = (ull*)  (sm + OFF_PWS);        // [2][96*32]
    int*   idxS = (int*)  (sm + OFF_IDX);        // [3][96]
    __shared__ int sLast;

    int t = threadIdx.x, lane = t & 31, w = t >> 5;   // w in 0..11
    int r0 = 8 * w;
    int cA = 2 * lane;

    // ---- prolog ----
    {
        int t0 = blockIdx.x;
        int t1 = t0 + PBLOCKS;                   // always < NT (>=42 tiles/block)
        const float* bsrc = bond + (size_t)t0 * 96 * BF;
        #pragma unroll
        for (int i = 0; i < 3; i++) {
            int c = t + 384 * i;
            if (c < 96 * BF / 4) cpasync16(braw + c * 4, bsrc + c * 4);
        }
        if (t < 256) cpasync16(SWs + t * 4, d_SW + (size_t)t0 * 8 * TWOA + t * 4);
        if (t < 24) {
            cpasync16(idxS + t * 4,      nidx + t0 * 96 + t * 4);
            cpasync16(idxS + 96 + t * 4, nidx + t1 * 96 + t * 4);
        }
        CP_COMMIT();                             // G1
        const float* wsrc = W + TWOA * TWOA;
        #pragma unroll
        for (int i = 0; i < 4; i++) {
            int c = t + 384 * i;
            if (c < BF * TWOA / 4) cpasync16(Ws + c * 4, wsrc + c * 4);
        }
        CP_COMMIT();                             // G2
        CP_WAIT(0);
        __syncthreads();
        // B0: PW gather for tile t0 (idx slot 0)
        #pragma unroll
        for (int i = 0; i < 4; i++) {
            int id = t + 384 * i;                // < 1536
            int row = id >> 4, ch = id & 15;
            cpasync16((char*)(PWs + row * 32) + ch * 16,
                      (const char*)(d_PW16 + (size_t)idxS[row] * 32) + ch * 16);
        }
        CP_COMMIT();                             // B0
    }

    float ls0 = 0, ls1 = 0, ls2 = 0, ls3 = 0;
    float lq0 = 0, lq1 = 0, lq2 = 0, lq3 = 0;

    int n = 0;
    for (int tile = blockIdx.x; tile < NT; tile += PBLOCKS, ++n) {
        int nt1 = tile + PBLOCKS;
        bool more = nt1 < NT;

        CP_WAIT(1);          // A_n done (braw/SW/idx for this tile); B_n may still be in flight
        __syncthreads();

        // transpose braw[r][k] -> bT[k][r]
        #pragma unroll
        for (int i = 0; i < 11; i++) {
            int id = t + 384 * i;
            if (id < 96 * BF) {
                int k = id / 96, r = id - 96 * k;
                bT[k * BT_PAD + r] = braw[r * BF + k];
            }
        }
        __syncthreads();     // braw free

        if (more) {
            // A_{n+1}: bond + SW + idx(n+2)
            const float* bsrc = bond + (size_t)nt1 * 96 * BF;
            #pragma unroll
            for (int i = 0; i < 3; i++) {
                int c = t + 384 * i;
                if (c < 96 * BF / 4) cpasync16(braw + c * 4, bsrc + c * 4);
            }
            if (t < 256) cpasync16(SWs + ((n + 1) & 1) * 1024 + t * 4,
                                   d_SW + (size_t)nt1 * 8 * TWOA + t * 4);
            int nt2 = nt1 + PBLOCKS;
            if (nt2 < NT && t < 24)
                cpasync16(idxS + ((n + 2) % 3) * 96 + t * 4, nidx + nt2 * 96 + t * 4);
            CP_COMMIT();
            // B_{n+1}: PW gather via idx slot (n+1)%3
            const int* idn = idxS + ((n + 1) % 3) * 96;
            ull* pwd = PWs + ((n + 1) & 1) * 3072;
            #pragma unroll
            for (int i = 0; i < 4; i++) {
                int id = t + 384 * i;
                int row = id >> 4, ch = id & 15;
                cpasync16((char*)(pwd + row * 32) + ch * 16,
                          (const char*)(d_PW16 + (size_t)idn[row] * 32) + ch * 16);
            }
            CP_COMMIT();
        }

        // GEMM: acc[p] = row-pair (r0+2p, r0+2p+1), 4 cols each
        ull acc[4][4];
        #pragma unroll
        for (int p = 0; p < 4; p++)
            #pragma unroll
            for (int u = 0; u < 4; u++) acc[p][u] = 0ull;

        #pragma unroll
        for (int k = 0; k < BF; k++) {
            float2 wa = *(const float2*)&Ws[k * TWOA + cA];
            float2 wb = *(const float2*)&Ws[k * TWOA + 64 + cA];
            ull w0 = packdup(wa.x), w1 = packdup(wa.y);
            ull w2 = packdup(wb.x), w3 = packdup(wb.y);
            const char* brow = (const char*)(bT + k * BT_PAD + r0);
            ulonglong2 q0 = *(const ulonglong2*)(brow);
            ulonglong2 q1 = *(const ulonglong2*)(brow + 16);
            ull bv0 = q0.x, bv1 = q0.y, bv2 = q1.x, bv3 = q1.y;
            ffma2(acc[0][0], bv0, w0); ffma2(acc[0][1], bv0, w1); ffma2(acc[0][2], bv0, w2); ffma2(acc[0][3], bv0, w3);
            ffma2(acc[1][0], bv1, w0); ffma2(acc[1][1], bv1, w1); ffma2(acc[1][2], bv1, w2); ffma2(acc[1][3], bv1, w3);
            ffma2(acc[2][0], bv2, w0); ffma2(acc[2][1], bv2, w1); ffma2(acc[2][2], bv2, w2); ffma2(acc[2][3], bv2, w3);
            ffma2(acc[3][0], bv3, w0); ffma2(acc[3][1], bv3, w1); ffma2(acc[3][2], bv3, w2); ffma2(acc[3][3], bv3, w3);
        }

        if (more) { CP_WAIT(2); } else { CP_WAIT(0); }   // B_n done
        __syncthreads();

        // epilogue: PW from smem (LDS.64), SW from smem, fp16 store, stats in regs
        const float* SWb = SWs + (n & 1) * 1024;
        const ull*   PWb = PWs + (n & 1) * 3072;
        ull* gbase = d_gated16 + (size_t)(tile * 96 + r0) * 32;

        #pragma unroll
        for (int p = 0; p < 4; p++) {
            float2 aA0 = unpk(acc[p][0]), aA1 = unpk(acc[p][1]);
            float2 aB0 = unpk(acc[p][2]), aB1 = unpk(acc[p][3]);
            #pragma unroll
            for (int s = 0; s < 2; s++) {
                int rr = r0 + 2 * p + s;          // local row 0..95
                int aLoc = rr / 12;               // local atom 0..7
                const float* swr = SWb + aLoc * TWOA;
                ull pk = PWb[rr * 32 + lane];
                unsigned plo = (unsigned)pk, phi = (unsigned)(pk >> 32);
                float2 pA = __half22float2(*(__half2*)&plo);
                float2 pB = __half22float2(*(__half2*)&phi);
                float2 swA = *(const float2*)(swr + cA);
                float2 swB = *(const float2*)(swr + 64 + cA);
                float v0 = (s ? aA0.y : aA0.x) + swA.x + pA.x;
                float v1 = (s ? aA1.y : aA1.x) + swA.y + pA.y;
                float v2 = (s ? aB0.y : aB0.x) + swB.x + pB.x;
                float v3 = (s ? aB1.y : aB1.x) + swB.y + pB.y;
                __half2 hA = __floats2half2_rn(v0, v1);
                __half2 hB = __floats2half2_rn(v2, v3);
                unsigned uA = *(unsigned*)&hA, uB = *(unsigned*)&hB;
                __stcs(gbase + (size_t)(2 * p + s) * 32 + lane, (ull)uA | ((ull)uB << 32));
                ls0 += v0; lq0 += v0 * v0;
                ls1 += v1; lq1 += v1 * v1;
                ls2 += v2; lq2 += v2 * v2;
                ls3 += v3; lq3 += v3 * v3;
            }
        }
    }

    // one stats reduction + atomic round per block (overlay braw region)
    __syncthreads();
    float* redS = (float*)(sm + OFF_RED);
    float* redQ = redS + 12 * TWOA;
    redS[w * TWOA + cA] = ls0;       redS[w * TWOA + cA + 1] = ls1;
    redS[w * TWOA + 64 + cA] = ls2;  redS[w * TWOA + 64 + cA + 1] = ls3;
    redQ[w * TWOA + cA] = lq0;       redQ[w * TWOA + cA + 1] = lq1;
    redQ[w * TWOA + 64 + cA] = lq2;  redQ[w * TWOA + 64 + cA + 1] = lq3;
    __syncthreads();
    if (t < TWOA) {
        float s = 0.0f, q = 0.0f;
        #pragma unroll
        for (int w2 = 0; w2 < 12; w2++) { s += redS[w2 * TWOA + t]; q += redQ[w2 * TWOA + t]; }
        atomicAdd(&d_s1[t], (double)s);
        atomicAdd(&d_q1[t], (double)q);
    }
    __syncthreads();
    if (t == 0) {
        __threadfence();
        unsigned old = atomicAdd(&d_c1, 1u);
        sLast = (old == PBLOCKS - 1) ? 1 : 0;
    }
    __syncthreads();
    if (sLast && t < TWOA) {
        double s = *((volatile double*)&d_s1[t]);
        double q = *((volatile double*)&d_q1[t]);
        double mean = s / NMF;
        double var  = q / NMF - mean * mean;
        float g = sc[t] * (float)(1.0 / sqrt(var + EPSBN));
        d_g1[t] = g;
        d_h1[t] = of[t] - (float)mean * g;
    }
}

// ---------------- kC: persistent; batched loads (MLP=6) per atom; BN2 stats in regs ----------
__global__ void __launch_bounds__(256) kC(const float* __restrict__ sc,
                                          const float* __restrict__ of) {
    __shared__ float rs[8][AF];
    __shared__ float rq[8][AF];
    __shared__ int sLast;
    int t = threadIdx.x;
    int lane = t & 31, w = t >> 5;
    int half = lane >> 4, q = lane & 15;
    int c0 = 4 * q;

    float4 G1A = *(const float4*)&d_g1[c0];
    float4 H1A = *(const float4*)&d_h1[c0];
    float4 G1B = *(const float4*)&d_g1[64 + c0];
    float4 H1B = *(const float4*)&d_h1[64 + c0];

    float as0 = 0, as1 = 0, as2 = 0, as3 = 0;
    float aq0 = 0, aq1 = 0, aq2 = 0, aq3 = 0;

    for (int tb = blockIdx.x; tb < NTC; tb += PB_C) {
        int aBase = tb * 32 + w * 4;
        #pragma unroll
        for (int u = 0; u < 4; u++) {
            int a = aBase + u;
            const uint4* gp = (const uint4*)(d_gated16 + (size_t)a * MNBR * 32);
            // batch all 6 loads first (MLP = 6)
            uint4 v[6];
            #pragma unroll
            for (int i = 0; i < 6; i++)
                v[i] = __ldcs(gp + (2 * i + half) * 16 + q);
            float s0 = 0.0f, s1 = 0.0f, s2 = 0.0f, s3 = 0.0f;
            #pragma unroll
            for (int i = 0; i < 6; i++) {
                float2 f01 = __half22float2(*(__half2*)&v[i].x);
                float2 c01 = __half22float2(*(__half2*)&v[i].y);
                float2 f23 = __half22float2(*(__half2*)&v[i].z);
                float2 c23 = __half22float2(*(__half2*)&v[i].w);
                float xf0 = f01.x * G1A.x + H1A.x;
                float xf1 = f01.y * G1A.y + H1A.y;
                float xf2 = f23.x * G1A.z + H1A.z;
                float xf3 = f23.y * G1A.w + H1A.w;
                float xc0 = c01.x * G1B.x + H1B.x;
                float xc1 = c01.y * G1B.y + H1B.y;
                float xc2 = c23.x * G1B.z + H1B.z;
                float xc3 = c23.y * G1B.w + H1B.w;
                s0 += sigmoidf_(xf0) * softplusf_(xc0);
                s1 += sigmoidf_(xf1) * softplusf_(xc1);
                s2 += sigmoidf_(xf2) * softplusf_(xc2);
                s3 += sigmoidf_(xf3) * softplusf_(xc3);
            }
            s0 += __shfl_xor_sync(0xffffffffu, s0, 16);
            s1 += __shfl_xor_sync(0xffffffffu, s1, 16);
            s2 += __shfl_xor_sync(0xffffffffu, s2, 16);
            s3 += __shfl_xor_sync(0xffffffffu, s3, 16);
            if (half == 0) {
                float4 sv; sv.x = s0; sv.y = s1; sv.z = s2; sv.w = s3;
                *(float4*)&d_summed[(size_t)a * AF + c0] = sv;
                as0 += s0; aq0 += s0 * s0;
                as1 += s1; aq1 += s1 * s1;
                as2 += s2; aq2 += s2 * s2;
                as3 += s3; aq3 += s3 * s3;
            }
        }
    }

    if (half == 0) {
        float4 sv; sv.x = as0; sv.y = as1; sv.z = as2; sv.w = as3;
        *(float4*)&rs[w][c0] = sv;
        float4 qv; qv.x = aq0; qv.y = aq1; qv.z = aq2; qv.w = aq3;
        *(float4*)&rq[w][c0] = qv;
    }
    __syncthreads();
    if (t < AF) {
        float s = 0.0f, qq = 0.0f;
        #pragma unroll
        for (int r = 0; r < 8; r++) { s += rs[r][t]; qq += rq[r][t]; }
        atomicAdd(&d_s2[t], (double)s);
        atomicAdd(&d_q2[t], (double)qq);
    }
    __syncthreads();
    if (t == 0) {
        __threadfence();
        unsigned old = atomicAdd(&d_c2, 1u);
        sLast = (old == PB_C - 1) ? 1 : 0;
    }
    __syncthreads();
    if (sLast && t < AF) {
        double s = *((volatile double*)&d_s2[t]);
        double qq = *((volatile double*)&d_q2[t]);
        double mean = s / NF;
        double var  = qq / NF - mean * mean;
        float g = sc[t] * (float)(1.0 / sqrt(var + EPSBN));
        d_g2[t] = g;
        d_h2[t] = of[t] - (float)mean * g;
    }
}

// ---------------- kD: out = softplus(atom + BN2(summed)) ----------------
__global__ void __launch_bounds__(256) kD(const float* __restrict__ atom,
                                          float* __restrict__ out) {
    int i = blockIdx.x * 256 + threadIdx.x;
    int c = i & (AF - 1);
    float y = d_summed[i] * d_g2[c] + d_h2[c];
    out[i] = softplusf_(atom[i] + y);
}

// ---------------- launch ----------------
extern "C" void kernel_launch(void* const* d_in, const int* in_sizes, int n_in,
                              void* d_out, int out_size) {
    const int*   nidx = (const int*)  d_in[0];
    const float* atom = (const float*)d_in[1];
    const float* bond = (const float*)d_in[2];
    const float* W    = (const float*)d_in[3];
    const float* bias = (const float*)d_in[4];
    const float* bn1s = (const float*)d_in[5];
    const float* bn1o = (const float*)d_in[6];
    const float* bn2s = (const float*)d_in[7];
    const float* bn2o = (const float*)d_in[8];
    float* out = (float*)d_out;

    cudaFuncSetAttribute(kGemmStore, cudaFuncAttributeMaxDynamicSharedMemorySize, SMEM_BYTES);

    kInit<<<1, 128>>>();                                                     // slot 1
    kA<<<(NATOM + 127) / 128, 256>>>(atom, W, bias);                         // slot 2
    kPack<<<(NATOM * 32) / 256, 256>>>();                                    // slot 3
    kGemmStore<<<PBLOCKS, 384, SMEM_BYTES>>>(bond, nidx, W, bn1s, bn1o);     // slot 4 (ncu)
    kC<<<PB_C, 256>>>(bn2s, bn2o);                                           // slot 5
    kD<<<(NATOM * AF) / 256, 256>>>(atom, out);                              // slot 6
}